// round 13
// baseline (speedup 1.0000x reference)
#include <cuda_runtime.h>
#include <cuda_bf16.h>
#include <cstdint>
#include <math.h>

// Problem constants
#define BWIN   2048
#define SEQ    64
#define DIM    256
#define HEADS  8
#define HD     32
#define NW     64
#define KDIM   256
#define TBL    225
#define CPBH   512

// Scratch (device globals)
__device__ float g_Q[BWIN * HEADS * SEQ * HD];
__device__ float g_K[BWIN * HEADS * SEQ * HD];
__device__ float g_V[BWIN * HEADS * SEQ * HD];
__device__ float g_table[TBL * HEADS];
__device__ float g_bias[HEADS * SEQ * SEQ];
__device__ float g_bm[NW * HEADS * SEQ * SEQ];     // fused bias+mask

// Pre-split (packed bf16 hi/lo, granule layout) operands
__device__ uint32_t g_Xs[(size_t)BWIN * SEQ * DIM];   // 128 MB
__device__ uint32_t g_Os[(size_t)BWIN * SEQ * DIM];   // 128 MB
__device__ uint32_t g_Ws[3 * DIM * DIM];
__device__ uint32_t g_Wp[DIM * DIM];

// SW128 swizzle on byte offsets (128B rows)
#define SWZ(b) ((b) ^ (((b) >> 3) & 0x70))

__device__ __forceinline__ uint32_t smem_u32(const void* p) {
    uint32_t a;
    asm("{ .reg .u64 t; cvta.to.shared.u64 t, %1; cvt.u32.u64 %0, t; }"
        : "=r"(a) : "l"(p));
    return a;
}

#define CP16(dst_u32, src_ptr) \
    asm volatile("cp.async.cg.shared.global [%0], [%1], 16;" \
        :: "r"(dst_u32), "l"(src_ptr) : "memory")
#define CP_COMMIT() asm volatile("cp.async.commit_group;" ::: "memory")
#define CP_WAIT0()  asm volatile("cp.async.wait_group 0;" ::: "memory")
#define CP_WAIT1()  asm volatile("cp.async.wait_group 1;" ::: "memory")

// bf16 2-level split of two floats, packed as k-pair words (f0 in low half)
__device__ __forceinline__ void split2_bf(float f0, float f1,
                                          uint32_t& hi, uint32_t& lo)
{
    __nv_bfloat16 h0 = __float2bfloat16_rn(f0);
    __nv_bfloat16 h1 = __float2bfloat16_rn(f1);
    float r0 = f0 - __bfloat162float(h0);
    float r1 = f1 - __bfloat162float(h1);
    __nv_bfloat16 l0 = __float2bfloat16_rn(r0);
    __nv_bfloat16 l1 = __float2bfloat16_rn(r1);
    hi = (uint32_t)__bfloat16_as_ushort(h0) | ((uint32_t)__bfloat16_as_ushort(h1) << 16);
    lo = (uint32_t)__bfloat16_as_ushort(l0) | ((uint32_t)__bfloat16_as_ushort(l1) << 16);
}

__device__ __forceinline__ void mma16816(float* c,
    uint32_t a0, uint32_t a1, uint32_t a2, uint32_t a3,
    uint32_t b0, uint32_t b1)
{
    asm volatile(
        "mma.sync.aligned.m16n8k16.row.col.f32.bf16.bf16.f32 "
        "{%0,%1,%2,%3},{%4,%5,%6,%7},{%8,%9},{%0,%1,%2,%3};"
        : "+f"(c[0]), "+f"(c[1]), "+f"(c[2]), "+f"(c[3])
        : "r"(a0), "r"(a1), "r"(a2), "r"(a3), "r"(b0), "r"(b1));
}

// ---------------------------------------------------------------------------
// split_pack: fp32 rows -> packed bf16 hi/lo granule layout.
// Granule = 8 consecutive floats -> 8 words:
//   [hi p0, hi p1, lo p0, lo p1, hi p2, hi p3, lo p2, lo p3]
// Byte-identical to the R11 split-at-STS smem image.
// ---------------------------------------------------------------------------
__global__ __launch_bounds__(256) void split_pack(
    const float* __restrict__ src, uint32_t* __restrict__ dst, int n_granules)
{
    int gidx = blockIdx.x * 256 + threadIdx.x;
    if (gidx >= n_granules) return;
    const float4* s = (const float4*)(src + (size_t)gidx * 8);
    float4 v0 = s[0], v1 = s[1];
    uint32_t h0, l0, h1, l1, h2, l2, h3, l3;
    split2_bf(v0.x, v0.y, h0, l0);
    split2_bf(v0.z, v0.w, h1, l1);
    split2_bf(v1.x, v1.y, h2, l2);
    split2_bf(v1.z, v1.w, h3, l3);
    uint4* d = (uint4*)(dst + (size_t)gidx * 8);
    d[0] = make_uint4(h0, h1, l0, l1);
    d[1] = make_uint4(h2, h3, l2, l3);
}

// ---------------------------------------------------------------------------
// Kernel 1: CPB MLP
// ---------------------------------------------------------------------------
__global__ __launch_bounds__(128) void cpb_table_kernel(
    const float* __restrict__ w1, const float* __restrict__ b1,
    const float* __restrict__ w2, const float* __restrict__ coords)
{
    int p = blockIdx.x;
    float c0 = coords[2 * p + 0];
    float c1 = coords[2 * p + 1];
    float acc[HEADS];
#pragma unroll
    for (int h = 0; h < HEADS; ++h) acc[h] = 0.f;

    for (int j = threadIdx.x; j < CPBH; j += 128) {
        float hid = fmaf(w1[2 * j], c0, fmaf(w1[2 * j + 1], c1, b1[j]));
        hid = fmaxf(hid, 0.f);
#pragma unroll
        for (int h = 0; h < HEADS; ++h)
            acc[h] = fmaf(hid, w2[h * CPBH + j], acc[h]);
    }
    int lane = threadIdx.x & 31, warp = threadIdx.x >> 5;
#pragma unroll
    for (int h = 0; h < HEADS; ++h)
#pragma unroll
        for (int off = 16; off; off >>= 1)
            acc[h] += __shfl_xor_sync(0xffffffffu, acc[h], off);

    __shared__ float red[4][HEADS];
    if (lane == 0)
#pragma unroll
        for (int h = 0; h < HEADS; ++h) red[warp][h] = acc[h];
    __syncthreads();
    if (threadIdx.x < HEADS) {
        float s = red[0][threadIdx.x] + red[1][threadIdx.x] +
                  red[2][threadIdx.x] + red[3][threadIdx.x];
        g_table[p * HEADS + threadIdx.x] = s;
    }
}

// ---------------------------------------------------------------------------
// Kernel 2: bias gather + 16*sigmoid
// ---------------------------------------------------------------------------
__global__ __launch_bounds__(256) void bias_gather_kernel(const int* __restrict__ rel_idx)
{
    int i = blockIdx.x * 256 + threadIdx.x;
    if (i >= HEADS * SEQ * SEQ) return;
    int h = i >> 12;
    int ij = i & 4095;
    float t = g_table[rel_idx[ij] * HEADS + h];
    g_bias[i] = 16.f / (1.f + expf(-t));
}

// ---------------------------------------------------------------------------
// Kernel 2b: fuse bias[h] + mask[w] -> g_bm[w][h][ij]
// ---------------------------------------------------------------------------
__global__ __launch_bounds__(256) void bm_fuse_kernel(const float* __restrict__ mask)
{
    int i = blockIdx.x * 256 + threadIdx.x;
    if (i >= NW * HEADS * SEQ * SEQ) return;
    int wh = i >> 12;
    int ij = i & 4095;
    int w = wh >> 3, h = wh & 7;
    g_bm[i] = g_bias[h * 4096 + ij] + mask[w * 4096 + ij];
}

// ---------------------------------------------------------------------------
// 3-term bf16 mma.sync GEMM, pre-split operands, cp.async double-buffered.
// CTA: 128x128 tile, 128 threads (4 warps of 64x64), BK=32, K=256 (8 stages).
// smem: stage s at s*32768: A 16KB, B 16KB. Total 64KB.
// Stage = pure cp.async of pre-packed rows into SW128-swizzled smem.
// ---------------------------------------------------------------------------
#define GSMEM_TOTAL 65536

__global__ __launch_bounds__(128, 2) void mma_gemm(
    const float* __restrict__ q_bias, const float* __restrict__ v_bias,
    const float* __restrict__ pb, float* __restrict__ out, int mode)
{
    extern __shared__ char sm[];
    uint32_t sb = smem_u32(sm);
    const uint32_t* As = (mode == 0) ? g_Xs : g_Os;
    const uint32_t* Bsrc = (mode == 0) ? g_Ws : g_Wp;
    int tid = threadIdx.x;
    int lane = tid & 31, warp = tid >> 5;
    int m0 = blockIdx.y * 128;
    int n0 = blockIdx.x * 128;
    int wm = (warp >> 1) * 64;
    int wn = (warp & 1) * 64;

    float acc[4][8][4];
#pragma unroll
    for (int mi = 0; mi < 4; ++mi)
#pragma unroll
        for (int ni = 0; ni < 8; ++ni)
#pragma unroll
            for (int q = 0; q < 4; ++q) acc[mi][ni][q] = 0.f;

    int g = lane >> 2;       // 0..7 row group
    int tk = lane & 3;       // 0..3 k-pair in group

#define ISSUE_STAGE(c) do { \
    uint32_t dbuf = sb + (uint32_t)(((c) & 1) * 32768); \
    const uint32_t* arow = As + (size_t)(m0 + tid) * 256 + (c) * 32; \
    const uint32_t* brow = Bsrc + (size_t)(n0 + tid) * 256 + (c) * 32; \
    _Pragma("unroll") \
    for (int gp = 0; gp < 4; ++gp) { \
        uint32_t o_ = (uint32_t)(tid * 128 + gp * 32); \
        CP16(dbuf + SWZ(o_), arow + gp * 8); \
        CP16(dbuf + SWZ(o_ + 16u), arow + gp * 8 + 4); \
        CP16(dbuf + 16384u + SWZ(o_), brow + gp * 8); \
        CP16(dbuf + 16384u + SWZ(o_ + 16u), brow + gp * 8 + 4); \
    } \
    CP_COMMIT(); \
} while (0)

    ISSUE_STAGE(0);

    for (int c = 0; c < 8; ++c) {
        if (c < 7) { ISSUE_STAGE(c + 1); CP_WAIT1(); }
        else       { CP_WAIT0(); }
        __syncthreads();

        const char* sA = sm + (c & 1) * 32768;
        const char* sB = sA + 16384;
#pragma unroll
        for (int s = 0; s < 2; ++s) {
            uint32_t Ah[4][4], Al[4][4];
#pragma unroll
            for (int mi = 0; mi < 4; ++mi) {
                int r0 = wm + mi * 16 + g;
                int r1 = r0 + 8;
                uint32_t oa0 = (uint32_t)(2 * s) * 32u + ((tk >> 1) * 16u) + ((tk & 1) * 4u);
                uint32_t oa2 = oa0 + 32u;
                uint32_t b00 = SWZ((uint32_t)(r0 * 128) + oa0);
                uint32_t b10 = SWZ((uint32_t)(r1 * 128) + oa0);
                uint32_t b01 = SWZ((uint32_t)(r0 * 128) + oa2);
                uint32_t b11 = SWZ((uint32_t)(r1 * 128) + oa2);
                Ah[mi][0] = *(const uint32_t*)(sA + b00);
                Ah[mi][1] = *(const uint32_t*)(sA + b10);
                Ah[mi][2] = *(const uint32_t*)(sA + b01);
                Ah[mi][3] = *(const uint32_t*)(sA + b11);
                Al[mi][0] = *(const uint32_t*)(sA + b00 + 8);
                Al[mi][1] = *(const uint32_t*)(sA + b10 + 8);
                Al[mi][2] = *(const uint32_t*)(sA + b01 + 8);
                Al[mi][3] = *(const uint32_t*)(sA + b11 + 8);
            }
#pragma unroll
            for (int ni = 0; ni < 8; ++ni) {
                int nr = wn + ni * 8 + g;
                uint32_t ob0 = (uint32_t)(2 * s) * 32u + ((tk >> 1) * 16u) + ((tk & 1) * 4u);
                uint32_t bb0 = SWZ((uint32_t)(nr * 128) + ob0);
                uint32_t bb1 = SWZ((uint32_t)(nr * 128) + ob0 + 32u);
                uint32_t bh0 = *(const uint32_t*)(sB + bb0);
                uint32_t bh1 = *(const uint32_t*)(sB + bb1);
                uint32_t bl0 = *(const uint32_t*)(sB + bb0 + 8);
                uint32_t bl1 = *(const uint32_t*)(sB + bb1 + 8);
#pragma unroll
                for (int mi = 0; mi < 4; ++mi) {
                    mma16816(acc[mi][ni], Ah[mi][0], Ah[mi][1], Ah[mi][2], Ah[mi][3], bh0, bh1);
                    mma16816(acc[mi][ni], Al[mi][0], Al[mi][1], Al[mi][2], Al[mi][3], bh0, bh1);
                    mma16816(acc[mi][ni], Ah[mi][0], Ah[mi][1], Ah[mi][2], Ah[mi][3], bl0, bl1);
                }
            }
        }
        __syncthreads();
    }

    // Epilogue
#pragma unroll
    for (int mi = 0; mi < 4; ++mi) {
#pragma unroll
        for (int ni = 0; ni < 8; ++ni) {
            int r = m0 + wm + mi * 16 + g;
            int c = n0 + wn + ni * 8 + 2 * tk;
            if (mode == 0) {
                int which = c >> 8;
                int h = (c >> 5) & 7;
                int d = c & 31;
                float b0, b1;
                if (which == 0)      { b0 = q_bias[c];       b1 = q_bias[c + 1]; }
                else if (which == 2) { b0 = v_bias[c - 512]; b1 = v_bias[c - 511]; }
                else                 { b0 = 0.f; b1 = 0.f; }
                float* baseP = (which == 0) ? g_Q : (which == 1) ? g_K : g_V;
                int bw0 = r >> 6, n_0 = r & 63;
                int bw1 = (r + 8) >> 6, n_1 = (r + 8) & 63;
                float2 v0 = make_float2(acc[mi][ni][0] + b0, acc[mi][ni][1] + b1);
                float2 v1 = make_float2(acc[mi][ni][2] + b0, acc[mi][ni][3] + b1);
                *(float2*)(baseP + (size_t)((bw0 * 8 + h) * 64 + n_0) * 32 + d) = v0;
                *(float2*)(baseP + (size_t)((bw1 * 8 + h) * 64 + n_1) * 32 + d) = v1;
            } else {
                float b0 = pb[c], b1 = pb[c + 1];
                float2 v0 = make_float2(acc[mi][ni][0] + b0, acc[mi][ni][1] + b1);
                float2 v1 = make_float2(acc[mi][ni][2] + b0, acc[mi][ni][3] + b1);
                *(float2*)(out + (size_t)r * 256 + c) = v0;
                *(float2*)(out + (size_t)(r + 8) * 256 + c) = v1;
            }
        }
    }
}

// ---------------------------------------------------------------------------
// bf16 mma attention (R12-proven), epilogue now writes packed-split g_Os.
// CTA = 2 heads of one window (128 thr). Grid = BWIN*4.
// ---------------------------------------------------------------------------
#define ATT_HEAD_WORDS 7424
#define ATT_SMEM_BYTES (2 * ATT_HEAD_WORDS * 4)

__global__ __launch_bounds__(128) void attn_bf16(const float* __restrict__ logit_scale)
{
    extern __shared__ uint32_t smw[];
    int tid = threadIdx.x;
    int lane = tid & 31, warp = tid >> 5;
    int b = blockIdx.x >> 2;
    int h = ((blockIdx.x & 3) << 1) + (warp >> 1);
    int hp = warp >> 1;
    int wp = warp & 1;
    int wrow = wp * 32;
    int g = lane >> 2, tk = lane & 3;

    uint32_t* Qh = smw + hp * ATT_HEAD_WORDS;
    uint32_t* Ql = Qh + 1280;
    uint32_t* Kh = Ql + 1280;
    uint32_t* Kl = Kh + 1280;
    uint32_t* VTh = Kl + 1280;
    uint32_t* VTl = VTh + 1152;

    const float* Qg = g_Q + (size_t)(b * 8 + h) * 2048;
    const float* Kg = g_K + (size_t)(b * 8 + h) * 2048;
    const float* Vg = g_V + (size_t)(b * 8 + h) * 2048;

    // ---- stage Q,K: LDG -> L2-normalize (16-lane reduce) -> split -> STS ----
    {
        int half = lane >> 4;
        int t = lane & 15;
#pragma unroll
        for (int rr = 0; rr < 16; ++rr) {
            int r = wrow + rr * 2 + half;
            float2 qv = *(const float2*)(Qg + r * 32 + 2 * t);
            float ss = qv.x * qv.x + qv.y * qv.y;
            ss += __shfl_xor_sync(0xffffffffu, ss, 8, 16);
            ss += __shfl_xor_sync(0xffffffffu, ss, 4, 16);
            ss += __shfl_xor_sync(0xffffffffu, ss, 2, 16);
            ss += __shfl_xor_sync(0xffffffffu, ss, 1, 16);
            float inv = 1.f / fmaxf(sqrtf(ss), 1e-12f);
            uint32_t hw, lw;
            split2_bf(qv.x * inv, qv.y * inv, hw, lw);
            Qh[r * 20 + t] = hw;
            Ql[r * 20 + t] = lw;

            float2 kv = *(const float2*)(Kg + r * 32 + 2 * t);
            ss = kv.x * kv.x + kv.y * kv.y;
            ss += __shfl_xor_sync(0xffffffffu, ss, 8, 16);
            ss += __shfl_xor_sync(0xffffffffu, ss, 4, 16);
            ss += __shfl_xor_sync(0xffffffffu, ss, 2, 16);
            ss += __shfl_xor_sync(0xffffffffu, ss, 1, 16);
            inv = 1.f / fmaxf(sqrtf(ss), 1e-12f);
            split2_bf(kv.x * inv, kv.y * inv, hw, lw);
            Kh[r * 20 + t] = hw;
            Kl[r * 20 + t] = lw;
        }
#pragma unroll
        for (int i = 0; i < 16; ++i) {
            int jp = wp * 16 + i;
            float v0 = Vg[(2 * jp) * 32 + lane];
            float v1 = Vg[(2 * jp + 1) * 32 + lane];
            uint32_t hw, lw;
            split2_bf(v0, v1, hw, lw);
            VTh[lane * 36 + jp] = hw;
            VTl[lane * 36 + jp] = lw;
        }
    }
    __syncthreads();

    float sc = __expf(fminf(logit_scale[h], 4.6051701859880913f));

    // ---- QK^T ----
    float acc[2][8][4];
#pragma unroll
    for (int mi = 0; mi < 2; ++mi)
#pragma unroll
        for (int ni = 0; ni < 8; ++ni)
#pragma unroll
            for (int q = 0; q < 4; ++q) acc[mi][ni][q] = 0.f;

#pragma unroll
    for (int s = 0; s < 2; ++s) {
        int kp0 = 8 * s + tk, kp1 = kp0 + 4;
        uint32_t Ah[2][4], Al[2][4];
#pragma unroll
        for (int mi = 0; mi < 2; ++mi) {
            int r0 = wrow + mi * 16 + g;
            int r1 = r0 + 8;
            Ah[mi][0] = Qh[r0 * 20 + kp0];
            Ah[mi][1] = Qh[r1 * 20 + kp0];
            Ah[mi][2] = Qh[r0 * 20 + kp1];
            Ah[mi][3] = Qh[r1 * 20 + kp1];
            Al[mi][0] = Ql[r0 * 20 + kp0];
            Al[mi][1] = Ql[r1 * 20 + kp0];
            Al[mi][2] = Ql[r0 * 20 + kp1];
            Al[mi][3] = Ql[r1 * 20 + kp1];
        }
#pragma unroll
        for (int ni = 0; ni < 8; ++ni) {
            int n = ni * 8 + g;
            uint32_t bh0 = Kh[n * 20 + kp0];
            uint32_t bh1 = Kh[n * 20 + kp1];
            uint32_t bl0 = Kl[n * 20 + kp0];
            uint32_t bl1 = Kl[n * 20 + kp1];
#pragma unroll
            for (int mi = 0; mi < 2; ++mi) {
                mma16816(acc[mi][ni], Ah[mi][0], Ah[mi][1], Ah[mi][2], Ah[mi][3], bh0, bh1);
                mma16816(acc[mi][ni], Al[mi][0], Al[mi][1], Al[mi][2], Al[mi][3], bh0, bh1);
                mma16816(acc[mi][ni], Ah[mi][0], Ah[mi][1], Ah[mi][2], Ah[mi][3], bl0, bl1);
            }
        }
    }

    // ---- logits + softmax ----
    const float* bm = g_bm + (size_t)(((b & (NW - 1)) * 8 + h)) * 4096;
#pragma unroll
    for (int mi = 0; mi < 2; ++mi) {
        int rA = wrow + mi * 16 + g;
        int rB = rA + 8;
        float mxA = -1e30f, mxB = -1e30f;
#pragma unroll
        for (int ni = 0; ni < 8; ++ni) {
            int c = ni * 8 + 2 * tk;
            float2 bA = *(const float2*)(bm + rA * 64 + c);
            float2 bB = *(const float2*)(bm + rB * 64 + c);
            acc[mi][ni][0] = fmaf(sc, acc[mi][ni][0], bA.x);
            acc[mi][ni][1] = fmaf(sc, acc[mi][ni][1], bA.y);
            acc[mi][ni][2] = fmaf(sc, acc[mi][ni][2], bB.x);
            acc[mi][ni][3] = fmaf(sc, acc[mi][ni][3], bB.y);
            mxA = fmaxf(mxA, fmaxf(acc[mi][ni][0], acc[mi][ni][1]));
            mxB = fmaxf(mxB, fmaxf(acc[mi][ni][2], acc[mi][ni][3]));
        }
        mxA = fmaxf(mxA, __shfl_xor_sync(0xffffffffu, mxA, 1));
        mxA = fmaxf(mxA, __shfl_xor_sync(0xffffffffu, mxA, 2));
        mxB = fmaxf(mxB, __shfl_xor_sync(0xffffffffu, mxB, 1));
        mxB = fmaxf(mxB, __shfl_xor_sync(0xffffffffu, mxB, 2));
        float sA = 0.f, sB = 0.f;
#pragma unroll
        for (int ni = 0; ni < 8; ++ni) {
            acc[mi][ni][0] = __expf(acc[mi][ni][0] - mxA);
            acc[mi][ni][1] = __expf(acc[mi][ni][1] - mxA);
            acc[mi][ni][2] = __expf(acc[mi][ni][2] - mxB);
            acc[mi][ni][3] = __expf(acc[mi][ni][3] - mxB);
            sA += acc[mi][ni][0] + acc[mi][ni][1];
            sB += acc[mi][ni][2] + acc[mi][ni][3];
        }
        sA += __shfl_xor_sync(0xffffffffu, sA, 1);
        sA += __shfl_xor_sync(0xffffffffu, sA, 2);
        sB += __shfl_xor_sync(0xffffffffu, sB, 1);
        sB += __shfl_xor_sync(0xffffffffu, sB, 2);
        float iA = 1.f / sA, iB = 1.f / sB;
#pragma unroll
        for (int ni = 0; ni < 8; ++ni) {
            acc[mi][ni][0] *= iA;
            acc[mi][ni][1] *= iA;
            acc[mi][ni][2] *= iB;
            acc[mi][ni][3] *= iB;
        }
    }

    // ---- AV: P from registers, V from VT smem ----
    float o[2][4][4];
#pragma unroll
    for (int mi = 0; mi < 2; ++mi)
#pragma unroll
        for (int ni = 0; ni < 4; ++ni)
#pragma unroll
            for (int q = 0; q < 4; ++q) o[mi][ni][q] = 0.f;

#pragma unroll
    for (int s = 0; s < 4; ++s) {
        int kp0 = 8 * s + tk, kp1 = kp0 + 4;
        uint32_t vh0[4], vh1[4], vl0[4], vl1[4];
#pragma unroll
        for (int ni = 0; ni < 4; ++ni) {
            int n = ni * 8 + g;
            vh0[ni] = VTh[n * 36 + kp0];
            vh1[ni] = VTh[n * 36 + kp1];
            vl0[ni] = VTl[n * 36 + kp0];
            vl1[ni] = VTl[n * 36 + kp1];
        }
#pragma unroll
        for (int mi = 0; mi < 2; ++mi) {
            uint32_t pah[4], pal[4];
            split2_bf(acc[mi][2 * s][0],     acc[mi][2 * s][1],     pah[0], pal[0]);
            split2_bf(acc[mi][2 * s][2],     acc[mi][2 * s][3],     pah[1], pal[1]);
            split2_bf(acc[mi][2 * s + 1][0], acc[mi][2 * s + 1][1], pah[2], pal[2]);
            split2_bf(acc[mi][2 * s + 1][2], acc[mi][2 * s + 1][3], pah[3], pal[3]);
#pragma unroll
            for (int ni = 0; ni < 4; ++ni) {
                mma16816(o[mi][ni], pah[0], pah[1], pah[2], pah[3], vh0[ni], vh1[ni]);
                mma16816(o[mi][ni], pal[0], pal[1], pal[2], pal[3], vh0[ni], vh1[ni]);
                mma16816(o[mi][ni], pah[0], pah[1], pah[2], pah[3], vl0[ni], vl1[ni]);
            }
        }
    }

    // write O in packed-split layout (word row stride 256)
    uint32_t* OgW = g_Os + (size_t)(b * 64) * 256;
#pragma unroll
    for (int mi = 0; mi < 2; ++mi) {
        int r0 = wrow + mi * 16 + g;
        int r1 = r0 + 8;
#pragma unroll
        for (int ni = 0; ni < 4; ++ni) {
            // global column c = h*32 + ni*8 + 2*tk; granule = h*4 + ni; local pair j = tk
            uint32_t wbase = (uint32_t)((h * 4 + ni) * 8 + ((tk >> 1) << 2) + (tk & 1));
            uint32_t hw, lw;
            split2_bf(o[mi][ni][0], o[mi][ni][1], hw, lw);
            OgW[(size_t)r0 * 256 + wbase] = hw;
            OgW[(size_t)r0 * 256 + wbase + 2] = lw;
            split2_bf(o[mi][ni][2], o[mi][ni][3], hw, lw);
            OgW[(size_t)r1 * 256 + wbase] = hw;
            OgW[(size_t)r1 * 256 + wbase + 2] = lw;
        }
    }
}

// ---------------------------------------------------------------------------
extern "C" void kernel_launch(void* const* d_in, const int* in_sizes, int n_in,
                              void* d_out, int out_size)
{
    const float* x           = (const float*)d_in[0];
    const float* mask        = (const float*)d_in[1];
    const float* qkv_w       = (const float*)d_in[2];
    const float* q_bias      = (const float*)d_in[3];
    const float* v_bias      = (const float*)d_in[4];
    const float* logit_scale = (const float*)d_in[5];
    const float* cpb_w1      = (const float*)d_in[6];
    const float* cpb_b1      = (const float*)d_in[7];
    const float* cpb_w2      = (const float*)d_in[8];
    const float* proj_w      = (const float*)d_in[9];
    const float* proj_b      = (const float*)d_in[10];
    const float* coords      = (const float*)d_in[11];
    const int*   rel_idx     = (const int*)d_in[12];
    float* out = (float*)d_out;

    static int configured = 0;
    if (!configured) {
        cudaFuncSetAttribute(mma_gemm, cudaFuncAttributeMaxDynamicSharedMemorySize,
                             GSMEM_TOTAL);
        cudaFuncSetAttribute(attn_bf16, cudaFuncAttributeMaxDynamicSharedMemorySize,
                             ATT_SMEM_BYTES);
        configured = 1;
    }

    uint32_t* xs_ptr = nullptr;  // device-symbol pointers resolved inside kernels

    cpb_table_kernel<<<TBL, 128>>>(cpb_w1, cpb_b1, cpb_w2, coords);
    bias_gather_kernel<<<(HEADS * SEQ * SEQ + 255) / 256, 256>>>(rel_idx);
    bm_fuse_kernel<<<(NW * HEADS * SEQ * SEQ + 255) / 256, 256>>>(mask);

    // pre-split operands (dst via device symbols, src passed in)
    {
        // x: 131072 rows * 32 granules
        void* dst;
        cudaGetSymbolAddress(&dst, g_Xs);
        split_pack<<<(BWIN * SEQ * DIM / 8 + 255) / 256, 256>>>(x, (uint32_t*)dst,
                                                                BWIN * SEQ * DIM / 8);
        cudaGetSymbolAddress(&dst, g_Ws);
        split_pack<<<(3 * DIM * DIM / 8 + 255) / 256, 256>>>(qkv_w, (uint32_t*)dst,
                                                             3 * DIM * DIM / 8);
        cudaGetSymbolAddress(&dst, g_Wp);
        split_pack<<<(DIM * DIM / 8 + 255) / 256, 256>>>(proj_w, (uint32_t*)dst,
                                                         DIM * DIM / 8);
    }
    (void)xs_ptr;

    mma_gemm<<<dim3(6, 1024), 128, GSMEM_TOTAL>>>(q_bias, v_bias,
                                                  nullptr, nullptr, 0);
    attn_bf16<<<BWIN * 4, 128, ATT_SMEM_BYTES>>>(logit_scale);
    mma_gemm<<<dim3(2, 1024), 128, GSMEM_TOTAL>>>(nullptr, nullptr,
                                                  proj_b, out, 1);
}